// round 9
// baseline (speedup 1.0000x reference)
#include <cuda_runtime.h>
#include <cstdint>

#define BATCH 256
#define SEQ   512
#define DIM   512
#define HID   1024
#define NA    6
#define NS    4

typedef unsigned long long ull;

// ---------------------------------------------------------------------------
// Device scratch (static; no cudaMalloc allowed)
// ---------------------------------------------------------------------------
__device__ float    g_z[(size_t)SEQ * BATCH * HID];     // z [S][B][H]
__device__ unsigned g_bits[3][BATCH][HID / 32];         // spike bitmasks
__device__ unsigned g_barCount;
__device__ unsigned g_barGen;

#define GRID_SCAN 128

// ---------------------------------------------------------------------------
// Grid barrier (128 blocks, 1/SM on 148-SM chip -> all co-resident)
// ---------------------------------------------------------------------------
__device__ __forceinline__ void grid_barrier() {
    __threadfence();
    __syncthreads();
    if (threadIdx.x == 0) {
        unsigned gen = *(volatile unsigned*)&g_barGen;
        unsigned arr = atomicAdd(&g_barCount, 1u);
        if (arr == GRID_SCAN - 1) {
            g_barCount = 0;
            __threadfence();
            *(volatile unsigned*)&g_barGen = gen + 1u;
        } else {
            while (*(volatile unsigned*)&g_barGen == gen) { }
        }
    }
    __syncthreads();
}

// Predicated packed f32x2 add: a += v if bit != 0. Each 32-bit half rounds
// exactly like scalar add.rn.f32, which equals the reference's
// fma(spk=1.0, v, acc); fma(0, v, acc) == acc exactly (acc never -0.0).
__device__ __forceinline__ void madd(ull& a, ull v, unsigned bit) {
    asm("{\n\t"
        ".reg .pred p;\n\t"
        "setp.ne.u32 p, %1, 0;\n\t"
        "@p add.rn.f32x2 %0, %0, %2;\n\t"
        "}"
        : "+l"(a) : "r"(bit), "l"(v));
}

// ---------------------------------------------------------------------------
__global__ void init_kernel() {
    int i = blockIdx.x * blockDim.x + threadIdx.x;
    if (i < BATCH * (HID / 32)) ((unsigned*)g_bits[0])[i] = 0u;
    if (i == 0) { g_barCount = 0u; g_barGen = 0u; }
}

// ---------------------------------------------------------------------------
// Encode: z = relu(x @ W_enc + b_enc).
// FLAT ascending-k single-accumulator FFMA chain per element (bitwise equal
// to any non-split SIMT SGEMM), bias-add and relu separately rounded.
// ---------------------------------------------------------------------------
__global__ void __launch_bounds__(256) encode_kernel(
    const float* __restrict__ X, const float* __restrict__ W,
    const float* __restrict__ bias)
{
    __shared__ float As[16][128];   // [k][m]
    __shared__ float Bs[16][128];   // [k][n]

    const int bm = blockIdx.y;      // 0..1023
    const int bn = blockIdx.x;      // 0..7
    const int tid = threadIdx.x;
    const int trow = (tid >> 4) * 8;
    const int tcol = (tid & 15) * 8;

    const float* A0 = X + (size_t)bm * 128 * DIM;
    const float* B0 = W + bn * 128;

    float acc[8][8];
#pragma unroll
    for (int i = 0; i < 8; ++i)
#pragma unroll
        for (int j = 0; j < 8; ++j) acc[i][j] = 0.f;

    for (int kt = 0; kt < DIM; kt += 16) {
#pragma unroll
        for (int l = 0; l < 2; ++l) {
            int fidx = tid + l * 256;
            int ar = fidx >> 2, ak = (fidx & 3) * 4;
            float4 av = *(const float4*)(A0 + (size_t)ar * DIM + kt + ak);
            As[ak + 0][ar] = av.x; As[ak + 1][ar] = av.y;
            As[ak + 2][ar] = av.z; As[ak + 3][ar] = av.w;
            int br = fidx >> 5, bc = (fidx & 31) * 4;
            *(float4*)&Bs[br][bc] = *(const float4*)(B0 + (size_t)(kt + br) * HID + bc);
        }
        __syncthreads();
#pragma unroll
        for (int kk = 0; kk < 16; ++kk) {
            float ra[8], rb[8];
#pragma unroll
            for (int i = 0; i < 8; ++i) ra[i] = As[kk][trow + i];
#pragma unroll
            for (int j = 0; j < 8; ++j) rb[j] = Bs[kk][tcol + j];
#pragma unroll
            for (int i = 0; i < 8; ++i)
#pragma unroll
                for (int j = 0; j < 8; ++j)
                    acc[i][j] = __fmaf_rn(ra[i], rb[j], acc[i][j]);
        }
        __syncthreads();
    }

    const int m0 = bm * 128 + trow;
    const int n0 = bn * 128 + tcol;
    float bb[8];
#pragma unroll
    for (int j = 0; j < 8; ++j) bb[j] = bias[n0 + j];
#pragma unroll
    for (int i = 0; i < 8; ++i) {
        int m = m0 + i;
        int b = m >> 9;
        int s = m & 511;
        float* dst = g_z + ((size_t)s * BATCH + b) * HID + n0;
        float r[8];
#pragma unroll
        for (int j = 0; j < 8; ++j)
            r[j] = fmaxf(__fadd_rn(acc[i][j], bb[j]), 0.f);
        ((float4*)dst)[0] = make_float4(r[0], r[1], r[2], r[3]);
        ((float4*)dst)[1] = make_float4(r[4], r[5], r[6], r[7]);
    }
}

// ---------------------------------------------------------------------------
// Scan: persistent, 128 blocks x 256 threads. Block = 16 rows x 128 cols,
// thread = 4 rows x 2 adjacent cols.
// Bit layout (ballot-natural): word w covers cols j = (w>>1)*64 + (w&1) + 2*b.
//
// spk@V: FLAT strictly-ascending-j single-accumulator plain-FADD chain
// (even/odd words interleaved) — bitwise-matches a flat ascending-k fp32
// SIMT GEMM over the firing rows.
//
// Membrane: CONTRACTED leading term — fma(0.95, mem, z) — then +G, +bv, -rst
// each separately rounded (XLA:GPU fused-elementwise with LLVM fp contraction).
// ---------------------------------------------------------------------------
__global__ void __launch_bounds__(256, 1) scan_kernel(
    const float* __restrict__ V,      const float* __restrict__ b_v,
    const float* __restrict__ W_pol,  const float* __restrict__ b_pol,
    const float* __restrict__ W_size, const float* __restrict__ b_size,
    const float* __restrict__ W_val,  const float* __restrict__ b_val,
    float* __restrict__ out)
{
    __shared__ unsigned sbits[16][32];

    const int tid = threadIdx.x;
    const int bid = blockIdx.x;
    const int rg = bid >> 3;
    const int cg = bid & 7;
    const int r0 = rg * 16;
    const int c0 = cg * 128;
    const int q  = tid >> 6;
    const int p  = tid & 63;
    const int c  = c0 + p * 2;

    const int lane = tid & 31;
    const int wh   = (tid >> 5) & 1;
    const int gwbase = ((c0 + wh * 64) >> 6) * 2;

    float2 mem[4];
#pragma unroll
    for (int i = 0; i < 4; ++i) { mem[i].x = 0.f; mem[i].y = 0.f; }
    unsigned ps[4] = {0u, 0u, 0u, 0u};

    const float bv0 = b_v[c];
    const float bv1 = b_v[c + 1];
    const int q4 = q * 4;

    for (int t = 0; t < SEQ; ++t) {
        const unsigned* curbits = &g_bits[t % 3][0][0] + (size_t)r0 * 32;
        ((unsigned*)sbits)[tid]       = __ldcg(curbits + tid);
        ((unsigned*)sbits)[tid + 256] = __ldcg(curbits + tid + 256);
        __syncthreads();

        ull acc[4] = {0ull, 0ull, 0ull, 0ull};   // flat accumulators

#pragma unroll 1
        for (int g = 0; g < 16; ++g) {      // group g = 64 j's, ascending
            unsigned we0 = sbits[q4 + 0][2 * g], wo0 = sbits[q4 + 0][2 * g + 1];
            unsigned we1 = sbits[q4 + 1][2 * g], wo1 = sbits[q4 + 1][2 * g + 1];
            unsigned we2 = sbits[q4 + 2][2 * g], wo2 = sbits[q4 + 2][2 * g + 1];
            unsigned we3 = sbits[q4 + 3][2 * g], wo3 = sbits[q4 + 3][2 * g + 1];
            if ((we0 | wo0 | we1 | wo1 | we2 | wo2 | we3 | wo3) == 0u) continue;
            const ull* vp = (const ull*)(V + (size_t)(g * 64) * HID) + (c >> 1);
#pragma unroll
            for (int b = 0; b < 32; ++b) {
                ull ve = vp[(size_t)b * HID];              // j = 64g + 2b
                ull vo = vp[(size_t)b * HID + (HID / 2)];  // j = 64g + 2b + 1
                unsigned bit = 1u << b;
                madd(acc[0], ve, we0 & bit); madd(acc[0], vo, wo0 & bit);
                madd(acc[1], ve, we1 & bit); madd(acc[1], vo, wo1 & bit);
                madd(acc[2], ve, we2 & bit); madd(acc[2], vo, wo2 & bit);
                madd(acc[3], ve, we3 & bit); madd(acc[3], vo, wo3 & bit);
            }
        }

        // membrane: (((fma(0.95, mem, z) + G) + bv) - rst
        const float* zrow = g_z + ((size_t)t * BATCH + r0 + q4) * HID + c;
#pragma unroll
        for (int i = 0; i < 4; ++i) {
            float2 zz = *(const float2*)(zrow + (size_t)i * HID);
            float2 a  = *(float2*)&acc[i];
            float rst0 = (ps[i] & 1u) ? 1.0f : 0.0f;
            float rst1 = (ps[i] & 2u) ? 1.0f : 0.0f;
            float m0v = __fsub_rn(__fadd_rn(__fadd_rn(
                           __fmaf_rn(0.95f, mem[i].x, zz.x), a.x), bv0), rst0);
            float m1v = __fsub_rn(__fadd_rn(__fadd_rn(
                           __fmaf_rn(0.95f, mem[i].y, zz.y), a.y), bv1), rst1);
            mem[i].x = m0v; mem[i].y = m1v;
            ps[i] = (m0v > 1.0f ? 1u : 0u) | (m1v > 1.0f ? 2u : 0u);
        }

        unsigned* dst = &g_bits[(t + 1) % 3][0][0];
#pragma unroll
        for (int i = 0; i < 4; ++i) {
            unsigned be = __ballot_sync(0xffffffffu, (ps[i] & 1u) != 0u);
            unsigned bo = __ballot_sync(0xffffffffu, (ps[i] & 2u) != 0u);
            if (lane == 0) {
                int row = r0 + q4 + i;
                dst[row * 32 + gwbase + 0] = be;
                dst[row * 32 + gwbase + 1] = bo;
            }
        }

        grid_barrier();
    }

    // Heads: no feedback -> ulp-level order differences are harmless (~1e-7
    // relative, far under the 1e-3 threshold). Flat ascending-j chains.
    const unsigned* tail = &g_bits[2][0][0];   // 512 % 3 == 2
    if (tid < 22) {
        int r = bid * 2 + tid / 11;
        int o = tid % 11;
        const float* Wp; int stride; float bo_;
        if (o < 6)       { Wp = W_pol  + o;       stride = NA; bo_ = b_pol[o]; }
        else if (o < 10) { Wp = W_size + (o - 6); stride = NS; bo_ = b_size[o - 6]; }
        else             { Wp = W_val;            stride = 1;  bo_ = b_val[0]; }
        float s = 0.f;
        for (int j = 0; j < HID; ++j) {
            unsigned word = __ldcg(tail + r * 32 + ((j >> 6) * 2 + (j & 1)));
            if ((word >> ((j & 63) >> 1)) & 1u)
                s = __fadd_rn(s, Wp[(size_t)j * stride]);
        }
        float val = __fadd_rn(s, bo_);
        if (o < 6)       out[r * NA + o] = val;
        else if (o < 10) out[BATCH * NA + r * NS + (o - 6)] = val;
        else             out[BATCH * NA + BATCH * NS + r] = val;
    }
}

// ---------------------------------------------------------------------------
extern "C" void kernel_launch(void* const* d_in, const int* in_sizes, int n_in,
                              void* d_out, int out_size) {
    const float* x      = (const float*)d_in[0];
    const float* W_enc  = (const float*)d_in[1];
    const float* b_enc  = (const float*)d_in[2];
    const float* V      = (const float*)d_in[3];
    const float* b_v    = (const float*)d_in[4];
    const float* W_pol  = (const float*)d_in[5];
    const float* b_pol  = (const float*)d_in[6];
    const float* W_size = (const float*)d_in[7];
    const float* b_size = (const float*)d_in[8];
    const float* W_val  = (const float*)d_in[9];
    const float* b_val  = (const float*)d_in[10];
    float* out = (float*)d_out;

    init_kernel<<<32, 256>>>();

    dim3 eg(HID / 128, (BATCH * SEQ) / 128);
    encode_kernel<<<eg, 256>>>(x, W_enc, b_enc);

    scan_kernel<<<GRID_SCAN, 256>>>(V, b_v, W_pol, b_pol, W_size, b_size,
                                    W_val, b_val, out);
}

// round 11
// speedup vs baseline: 1.0471x; 1.0471x over previous
#include <cuda_runtime.h>
#include <cstdint>

#define BATCH 256
#define SEQ   512
#define DIM   512
#define HID   1024
#define NA    6
#define NS    4

typedef unsigned long long ull;

// ---------------------------------------------------------------------------
// Device scratch (static; no cudaMalloc allowed)
// ---------------------------------------------------------------------------
__device__ float    g_z[(size_t)SEQ * BATCH * HID];     // z [S][B][H]
__device__ unsigned g_bits[3][BATCH][HID / 32];         // spike bitmasks
__device__ unsigned g_barCount;                          // zero-init at load
__device__ unsigned g_barGen;                            // monotonic; eq-compare

#define GRID_SCAN 128

// ---------------------------------------------------------------------------
// Grid barrier (128 blocks, 1/SM on 148-SM chip -> all co-resident).
// Self-restoring across graph replays (count returns to 0, gen monotonic).
// ---------------------------------------------------------------------------
__device__ __forceinline__ void grid_barrier() {
    __threadfence();
    __syncthreads();
    if (threadIdx.x == 0) {
        unsigned gen = *(volatile unsigned*)&g_barGen;
        unsigned arr = atomicAdd(&g_barCount, 1u);
        if (arr == GRID_SCAN - 1) {
            g_barCount = 0;
            __threadfence();
            *(volatile unsigned*)&g_barGen = gen + 1u;
        } else {
            while (*(volatile unsigned*)&g_barGen == gen) { }
        }
    }
    __syncthreads();
}

// Predicated packed f32x2 add: a += v if bit != 0. Each 32-bit half rounds
// exactly like scalar add.rn.f32 == the reference's fma(1.0, v, acc) step;
// skipping (bit=0) is exact because fma(0, v, acc) == acc (acc never -0.0).
__device__ __forceinline__ void madd(ull& a, ull v, unsigned bit) {
    asm("{\n\t"
        ".reg .pred p;\n\t"
        "setp.ne.u32 p, %1, 0;\n\t"
        "@p add.rn.f32x2 %0, %0, %2;\n\t"
        "}"
        : "+l"(a) : "r"(bit), "l"(v));
}

// ---------------------------------------------------------------------------
// Encode: z = relu(x @ W_enc + b_enc).
// FLAT ascending-k single-accumulator FFMA chain per element (bitwise equal
// to the reference), bias-add and relu separately rounded.
// Register-prefetch double buffering; A-tile slots: 512 float4 per tile
// -> ar = fidx>>2 (rows 0..127), ak = (fidx&3)*4.  (R10 bug was >>1.)
// Block (0,0) additionally zeroes g_bits[0] (init merged; 2 launches/call).
// ---------------------------------------------------------------------------
__global__ void __launch_bounds__(256, 2) encode_kernel(
    const float* __restrict__ X, const float* __restrict__ W,
    const float* __restrict__ bias)
{
    __shared__ float As[16][128];   // [k][m]
    __shared__ float Bs[16][128];   // [k][n]

    const int bm = blockIdx.y;      // 0..1023
    const int bn = blockIdx.x;      // 0..7
    const int tid = threadIdx.x;

    // merged init: one block zeroes the spike bitmask buffer 0
    if (bm == 0 && bn == 0) {
        unsigned* bz = &g_bits[0][0][0];
#pragma unroll
        for (int l = 0; l < (BATCH * (HID / 32)) / 256; ++l)
            bz[tid + l * 256] = 0u;
    }

    const int trow = (tid >> 4) * 8;
    const int tcol = (tid & 15) * 8;

    const float* A0 = X + (size_t)bm * 128 * DIM;
    const float* B0 = W + bn * 128;

    // per-thread load slots (2 float4 per matrix per tile)
    // A tile: 128 rows x 16 k = 512 float4: ar = fidx>>2, ak = (fidx&3)*4
    const int ar0 = tid >> 2,          ak0 = (tid & 3) * 4;
    const int ar1 = (tid + 256) >> 2,  ak1 = ((tid + 256) & 3) * 4;
    // B tile: 16 rows x 128 cols = 512 float4: br = fidx>>5, bc = (fidx&31)*4
    const int br0 = tid >> 5,          bc0 = (tid & 31) * 4;
    const int br1 = (tid + 256) >> 5,  bc1 = ((tid + 256) & 31) * 4;

    float acc[8][8];
#pragma unroll
    for (int i = 0; i < 8; ++i)
#pragma unroll
        for (int j = 0; j < 8; ++j) acc[i][j] = 0.f;

    // prefetch tile 0
    float4 pa0 = *(const float4*)(A0 + (size_t)ar0 * DIM + 0 + ak0);
    float4 pa1 = *(const float4*)(A0 + (size_t)ar1 * DIM + 0 + ak1);
    float4 pb0 = *(const float4*)(B0 + (size_t)(0 + br0) * HID + bc0);
    float4 pb1 = *(const float4*)(B0 + (size_t)(0 + br1) * HID + bc1);

    for (int kt = 0; kt < DIM; kt += 16) {
        // store prefetched tile to smem
        As[ak0 + 0][ar0] = pa0.x; As[ak0 + 1][ar0] = pa0.y;
        As[ak0 + 2][ar0] = pa0.z; As[ak0 + 3][ar0] = pa0.w;
        As[ak1 + 0][ar1] = pa1.x; As[ak1 + 1][ar1] = pa1.y;
        As[ak1 + 2][ar1] = pa1.z; As[ak1 + 3][ar1] = pa1.w;
        *(float4*)&Bs[br0][bc0] = pb0;
        *(float4*)&Bs[br1][bc1] = pb1;
        __syncthreads();

        // issue next tile's loads (consumed after compute -> latency hidden)
        if (kt + 16 < DIM) {
            pa0 = *(const float4*)(A0 + (size_t)ar0 * DIM + (kt + 16) + ak0);
            pa1 = *(const float4*)(A0 + (size_t)ar1 * DIM + (kt + 16) + ak1);
            pb0 = *(const float4*)(B0 + (size_t)(kt + 16 + br0) * HID + bc0);
            pb1 = *(const float4*)(B0 + (size_t)(kt + 16 + br1) * HID + bc1);
        }

#pragma unroll
        for (int kk = 0; kk < 16; ++kk) {
            float ra[8], rb[8];
#pragma unroll
            for (int i = 0; i < 8; ++i) ra[i] = As[kk][trow + i];
#pragma unroll
            for (int j = 0; j < 8; ++j) rb[j] = Bs[kk][tcol + j];
#pragma unroll
            for (int i = 0; i < 8; ++i)
#pragma unroll
                for (int j = 0; j < 8; ++j)
                    acc[i][j] = __fmaf_rn(ra[i], rb[j], acc[i][j]);
        }
        __syncthreads();
    }

    const int m0 = bm * 128 + trow;
    const int n0 = bn * 128 + tcol;
    float bb[8];
#pragma unroll
    for (int j = 0; j < 8; ++j) bb[j] = bias[n0 + j];
#pragma unroll
    for (int i = 0; i < 8; ++i) {
        int m = m0 + i;
        int b = m >> 9;
        int s = m & 511;
        float* dst = g_z + ((size_t)s * BATCH + b) * HID + n0;
        float r[8];
#pragma unroll
        for (int j = 0; j < 8; ++j)
            r[j] = fmaxf(__fadd_rn(acc[i][j], bb[j]), 0.f);
        ((float4*)dst)[0] = make_float4(r[0], r[1], r[2], r[3]);
        ((float4*)dst)[1] = make_float4(r[4], r[5], r[6], r[7]);
    }
}

// ---------------------------------------------------------------------------
// Scan: persistent, 128 blocks x 256 threads. Block = 16 rows x 128 cols,
// thread = 4 rows x 2 adjacent cols.
// Bit layout (ballot-natural): word w covers cols j = (w>>1)*64 + (w&1) + 2*b.
//
// spk@V: FLAT strictly-ascending-j single-accumulator plain-FADD chain.
// Membrane: fma(0.95, mem, z) then +G, +bv, -rst each separately rounded.
// (Bitwise-frozen reference semantics from R9 — do not alter.)
// ---------------------------------------------------------------------------
__global__ void __launch_bounds__(256, 1) scan_kernel(
    const float* __restrict__ V,      const float* __restrict__ b_v,
    const float* __restrict__ W_pol,  const float* __restrict__ b_pol,
    const float* __restrict__ W_size, const float* __restrict__ b_size,
    const float* __restrict__ W_val,  const float* __restrict__ b_val,
    float* __restrict__ out)
{
    __shared__ unsigned sbits[16][32];

    const int tid = threadIdx.x;
    const int bid = blockIdx.x;
    const int rg = bid >> 3;
    const int cg = bid & 7;
    const int r0 = rg * 16;
    const int c0 = cg * 128;
    const int q  = tid >> 6;
    const int p  = tid & 63;
    const int c  = c0 + p * 2;

    const int lane = tid & 31;
    const int wh   = (tid >> 5) & 1;
    const int gwbase = ((c0 + wh * 64) >> 6) * 2;

    float2 mem[4];
#pragma unroll
    for (int i = 0; i < 4; ++i) { mem[i].x = 0.f; mem[i].y = 0.f; }
    unsigned ps[4] = {0u, 0u, 0u, 0u};

    const float bv0 = b_v[c];
    const float bv1 = b_v[c + 1];
    const int q4 = q * 4;

    for (int t = 0; t < SEQ; ++t) {
        // prefetch z early: independent of the madd loop, DRAM latency hides
        const float* zrow = g_z + ((size_t)t * BATCH + r0 + q4) * HID + c;
        float2 zz[4];
#pragma unroll
        for (int i = 0; i < 4; ++i)
            zz[i] = *(const float2*)(zrow + (size_t)i * HID);

        const unsigned* curbits = &g_bits[t % 3][0][0] + (size_t)r0 * 32;
        ((unsigned*)sbits)[tid]       = __ldcg(curbits + tid);
        ((unsigned*)sbits)[tid + 256] = __ldcg(curbits + tid + 256);
        __syncthreads();

        ull acc[4] = {0ull, 0ull, 0ull, 0ull};   // flat accumulators

#pragma unroll 1
        for (int g = 0; g < 16; ++g) {      // group g = 64 j's, ascending
            unsigned we0 = sbits[q4 + 0][2 * g], wo0 = sbits[q4 + 0][2 * g + 1];
            unsigned we1 = sbits[q4 + 1][2 * g], wo1 = sbits[q4 + 1][2 * g + 1];
            unsigned we2 = sbits[q4 + 2][2 * g], wo2 = sbits[q4 + 2][2 * g + 1];
            unsigned we3 = sbits[q4 + 3][2 * g], wo3 = sbits[q4 + 3][2 * g + 1];
            if ((we0 | wo0 | we1 | wo1 | we2 | wo2 | we3 | wo3) == 0u) continue;
            const ull* vp = (const ull*)(V + (size_t)(g * 64) * HID) + (c >> 1);
#pragma unroll
            for (int b = 0; b < 32; ++b) {
                ull ve = vp[(size_t)b * HID];              // j = 64g + 2b
                ull vo = vp[(size_t)b * HID + (HID / 2)];  // j = 64g + 2b + 1
                unsigned bit = 1u << b;
                madd(acc[0], ve, we0 & bit); madd(acc[0], vo, wo0 & bit);
                madd(acc[1], ve, we1 & bit); madd(acc[1], vo, wo1 & bit);
                madd(acc[2], ve, we2 & bit); madd(acc[2], vo, wo2 & bit);
                madd(acc[3], ve, we3 & bit); madd(acc[3], vo, wo3 & bit);
            }
        }

        // membrane: ((fma(0.95, mem, z) + G) + bv) - rst   (frozen semantics)
#pragma unroll
        for (int i = 0; i < 4; ++i) {
            float2 a = *(float2*)&acc[i];
            float rst0 = (ps[i] & 1u) ? 1.0f : 0.0f;
            float rst1 = (ps[i] & 2u) ? 1.0f : 0.0f;
            float m0v = __fsub_rn(__fadd_rn(__fadd_rn(
                           __fmaf_rn(0.95f, mem[i].x, zz[i].x), a.x), bv0), rst0);
            float m1v = __fsub_rn(__fadd_rn(__fadd_rn(
                           __fmaf_rn(0.95f, mem[i].y, zz[i].y), a.y), bv1), rst1);
            mem[i].x = m0v; mem[i].y = m1v;
            ps[i] = (m0v > 1.0f ? 1u : 0u) | (m1v > 1.0f ? 2u : 0u);
        }

        unsigned* dst = &g_bits[(t + 1) % 3][0][0];
#pragma unroll
        for (int i = 0; i < 4; ++i) {
            unsigned be = __ballot_sync(0xffffffffu, (ps[i] & 1u) != 0u);
            unsigned bo = __ballot_sync(0xffffffffu, (ps[i] & 2u) != 0u);
            if (lane == 0) {
                int row = r0 + q4 + i;
                dst[row * 32 + gwbase + 0] = be;
                dst[row * 32 + gwbase + 1] = bo;
            }
        }

        grid_barrier();
    }

    // Heads: no feedback -> ulp-level order differences harmless.
    const unsigned* tail = &g_bits[2][0][0];   // 512 % 3 == 2
    if (tid < 22) {
        int r = bid * 2 + tid / 11;
        int o = tid % 11;
        const float* Wp; int stride; float bo_;
        if (o < 6)       { Wp = W_pol  + o;       stride = NA; bo_ = b_pol[o]; }
        else if (o < 10) { Wp = W_size + (o - 6); stride = NS; bo_ = b_size[o - 6]; }
        else             { Wp = W_val;            stride = 1;  bo_ = b_val[0]; }
        float s = 0.f;
        for (int j = 0; j < HID; ++j) {
            unsigned word = __ldcg(tail + r * 32 + ((j >> 6) * 2 + (j & 1)));
            if ((word >> ((j & 63) >> 1)) & 1u)
                s = __fadd_rn(s, Wp[(size_t)j * stride]);
        }
        float val = __fadd_rn(s, bo_);
        if (o < 6)       out[r * NA + o] = val;
        else if (o < 10) out[BATCH * NA + r * NS + (o - 6)] = val;
        else             out[BATCH * NA + BATCH * NS + r] = val;
    }
}

// ---------------------------------------------------------------------------
// kernel_launch: 2 launches per call (init merged into encode) so the ncu
// capture slot (-s 5) lands on scan_kernel.
// ---------------------------------------------------------------------------
extern "C" void kernel_launch(void* const* d_in, const int* in_sizes, int n_in,
                              void* d_out, int out_size) {
    const float* x      = (const float*)d_in[0];
    const float* W_enc  = (const float*)d_in[1];
    const float* b_enc  = (const float*)d_in[2];
    const float* V      = (const float*)d_in[3];
    const float* b_v    = (const float*)d_in[4];
    const float* W_pol  = (const float*)d_in[5];
    const float* b_pol  = (const float*)d_in[6];
    const float* W_size = (const float*)d_in[7];
    const float* b_size = (const float*)d_in[8];
    const float* W_val  = (const float*)d_in[9];
    const float* b_val  = (const float*)d_in[10];
    float* out = (float*)d_out;

    dim3 eg(HID / 128, (BATCH * SEQ) / 128);
    encode_kernel<<<eg, 256>>>(x, W_enc, b_enc);

    scan_kernel<<<GRID_SCAN, 256>>>(V, b_v, W_pol, b_pol, W_size, b_size,
                                    W_val, b_val, out);
}

// round 12
// speedup vs baseline: 1.7947x; 1.7140x over previous
#include <cuda_runtime.h>
#include <cstdint>

#define BATCH 256
#define SEQ   512
#define DIM   512
#define HID   1024
#define NA    6
#define NS    4

typedef unsigned long long ull;

// ---------------------------------------------------------------------------
// Device scratch (static; no cudaMalloc allowed)
// ---------------------------------------------------------------------------
__device__ float    g_z[(size_t)SEQ * BATCH * HID];       // z [S][B][H]
__device__ __align__(16) unsigned g_bits[3][BATCH][HID / 32]; // spike bitmasks
__device__ unsigned g_barCount;                            // zero-init at load
__device__ unsigned g_barGen;                              // monotonic

#define GRID_SCAN 128
// dynamic smem: sbits[512] + scount[16]+pad[16] + slist[16][1024]
#define SMEM_SCAN ((512 + 32 + 16 * 1024) * 4)

// ---------------------------------------------------------------------------
// Grid barrier (128 blocks, 1/SM -> co-resident; self-restoring across replays)
// ---------------------------------------------------------------------------
__device__ __forceinline__ void grid_barrier() {
    __threadfence();
    __syncthreads();
    if (threadIdx.x == 0) {
        unsigned gen = *(volatile unsigned*)&g_barGen;
        unsigned arr = atomicAdd(&g_barCount, 1u);
        if (arr == GRID_SCAN - 1) {
            g_barCount = 0;
            __threadfence();
            *(volatile unsigned*)&g_barGen = gen + 1u;
        } else {
            while (*(volatile unsigned*)&g_barGen == gen) { }
        }
    }
    __syncthreads();
}

// Packed f32x2 add: each half rounds exactly like scalar add.rn.f32
// (== the reference's fma(1.0, v, acc) chain step).
__device__ __forceinline__ ull padd(ull a, ull b) {
    ull r;
    asm("add.rn.f32x2 %0, %1, %2;" : "=l"(r) : "l"(a), "l"(b));
    return r;
}

// spread 16 bits: bit i -> bit 4i of a 64-bit word
__device__ __forceinline__ ull spread4(unsigned h) {
    ull x = h;
    x = (x | (x << 24)) & 0x000000FF000000FFull;
    x = (x | (x << 12)) & 0x000F000F000F000Full;
    x = (x | (x << 6))  & 0x0303030303030303ull;
    x = (x | (x << 3))  & 0x1111111111111111ull;
    return x;
}

// ---------------------------------------------------------------------------
// Encode: z = relu(x @ W_enc + b_enc). FLAT ascending-k single-accumulator
// FFMA chain per element; bias-add and relu separately rounded. (Frozen.)
// Register-prefetch double buffering. Block (0,0) also zeroes g_bits[0].
// ---------------------------------------------------------------------------
__global__ void __launch_bounds__(256, 2) encode_kernel(
    const float* __restrict__ X, const float* __restrict__ W,
    const float* __restrict__ bias)
{
    __shared__ float As[16][128];
    __shared__ float Bs[16][128];

    const int bm = blockIdx.y;
    const int bn = blockIdx.x;
    const int tid = threadIdx.x;

    if (bm == 0 && bn == 0) {
        unsigned* bz = &g_bits[0][0][0];
#pragma unroll
        for (int l = 0; l < (BATCH * (HID / 32)) / 256; ++l)
            bz[tid + l * 256] = 0u;
    }

    const int trow = (tid >> 4) * 8;
    const int tcol = (tid & 15) * 8;

    const float* A0 = X + (size_t)bm * 128 * DIM;
    const float* B0 = W + bn * 128;

    const int ar0 = tid >> 2,          ak0 = (tid & 3) * 4;
    const int ar1 = (tid + 256) >> 2,  ak1 = ((tid + 256) & 3) * 4;
    const int br0 = tid >> 5,          bc0 = (tid & 31) * 4;
    const int br1 = (tid + 256) >> 5,  bc1 = ((tid + 256) & 31) * 4;

    float acc[8][8];
#pragma unroll
    for (int i = 0; i < 8; ++i)
#pragma unroll
        for (int j = 0; j < 8; ++j) acc[i][j] = 0.f;

    float4 pa0 = *(const float4*)(A0 + (size_t)ar0 * DIM + ak0);
    float4 pa1 = *(const float4*)(A0 + (size_t)ar1 * DIM + ak1);
    float4 pb0 = *(const float4*)(B0 + (size_t)br0 * HID + bc0);
    float4 pb1 = *(const float4*)(B0 + (size_t)br1 * HID + bc1);

    for (int kt = 0; kt < DIM; kt += 16) {
        As[ak0 + 0][ar0] = pa0.x; As[ak0 + 1][ar0] = pa0.y;
        As[ak0 + 2][ar0] = pa0.z; As[ak0 + 3][ar0] = pa0.w;
        As[ak1 + 0][ar1] = pa1.x; As[ak1 + 1][ar1] = pa1.y;
        As[ak1 + 2][ar1] = pa1.z; As[ak1 + 3][ar1] = pa1.w;
        *(float4*)&Bs[br0][bc0] = pb0;
        *(float4*)&Bs[br1][bc1] = pb1;
        __syncthreads();

        if (kt + 16 < DIM) {
            pa0 = *(const float4*)(A0 + (size_t)ar0 * DIM + (kt + 16) + ak0);
            pa1 = *(const float4*)(A0 + (size_t)ar1 * DIM + (kt + 16) + ak1);
            pb0 = *(const float4*)(B0 + (size_t)(kt + 16 + br0) * HID + bc0);
            pb1 = *(const float4*)(B0 + (size_t)(kt + 16 + br1) * HID + bc1);
        }

#pragma unroll
        for (int kk = 0; kk < 16; ++kk) {
            float ra[8], rb[8];
#pragma unroll
            for (int i = 0; i < 8; ++i) ra[i] = As[kk][trow + i];
#pragma unroll
            for (int j = 0; j < 8; ++j) rb[j] = Bs[kk][tcol + j];
#pragma unroll
            for (int i = 0; i < 8; ++i)
#pragma unroll
                for (int j = 0; j < 8; ++j)
                    acc[i][j] = __fmaf_rn(ra[i], rb[j], acc[i][j]);
        }
        __syncthreads();
    }

    const int m0 = bm * 128 + trow;
    const int n0 = bn * 128 + tcol;
    float bb[8];
#pragma unroll
    for (int j = 0; j < 8; ++j) bb[j] = bias[n0 + j];
#pragma unroll
    for (int i = 0; i < 8; ++i) {
        int m = m0 + i;
        int b = m >> 9;
        int s = m & 511;
        float* dst = g_z + ((size_t)s * BATCH + b) * HID + n0;
        float r[8];
#pragma unroll
        for (int j = 0; j < 8; ++j)
            r[j] = fmaxf(__fadd_rn(acc[i][j], bb[j]), 0.f);
        ((float4*)dst)[0] = make_float4(r[0], r[1], r[2], r[3]);
        ((float4*)dst)[1] = make_float4(r[4], r[5], r[6], r[7]);
    }
}

// ---------------------------------------------------------------------------
// Scan: persistent, 128 blocks x 256 threads. Block = 16 rows x 128 cols.
// Warp u owns rows {2u, 2u+1}; lane owns 4 adjacent cols (c = c0 + 4*lane).
//
// Bit layout: word (row, 4*cg + r), bit l  <->  col/j = 128*cg + 4*l + r.
// Per step: masks -> per-row ascending firing-index lists (byte offsets
// j*4096) in smem, then a pure FADD2 stream over LDG.128 V rows.
// Exactness: visits = exactly the firing j's in ascending order == the
// reference's flat ascending-k chain (fma(0,v,acc) identity). Membrane:
// fma(0.95, mem, z) then +G, +bv, -rst separately rounded. (Frozen.)
// ---------------------------------------------------------------------------
__global__ void __launch_bounds__(256, 1) scan_kernel(
    const float* __restrict__ V,      const float* __restrict__ b_v,
    const float* __restrict__ W_pol,  const float* __restrict__ b_pol,
    const float* __restrict__ W_size, const float* __restrict__ b_size,
    const float* __restrict__ W_val,  const float* __restrict__ b_val,
    float* __restrict__ out)
{
    extern __shared__ unsigned smx[];
    unsigned* sbits  = smx;            // [16][32]
    unsigned* scount = smx + 512;      // [16] (+16 pad)
    unsigned* slist  = smx + 544;      // [16][1024]

    const int tid  = threadIdx.x;
    const int bid  = blockIdx.x;
    const int rg   = bid >> 3;
    const int cg   = bid & 7;
    const int r0   = rg * 16;
    const int c0   = cg * 128;
    const int u    = tid >> 5;          // warp id 0..7 -> rows 2u, 2u+1
    const int lane = tid & 31;
    const int c    = c0 + 4 * lane;     // first of 4 adjacent cols

    const char* Vb = (const char*)V + (size_t)c * 4;

    float4 mem2[2];
    mem2[0] = make_float4(0.f, 0.f, 0.f, 0.f);
    mem2[1] = make_float4(0.f, 0.f, 0.f, 0.f);
    unsigned ps2[2] = {0u, 0u};         // 4 spike bits per row

    const float4 bv4 = *(const float4*)(b_v + c);

    for (int t = 0; t < SEQ; ++t) {
        // z prefetch (independent of everything below -> latency hidden)
        float4 zz[2];
#pragma unroll
        for (int rr = 0; rr < 2; ++rr)
            zz[rr] = *(const float4*)(g_z +
                       ((size_t)t * BATCH + r0 + 2 * u + rr) * HID + c);

        // stage this block's 16 rows of spike bits (512 words)
        const unsigned* curbits = &g_bits[t % 3][0][0] + (size_t)r0 * 32;
        sbits[tid]       = __ldcg(curbits + tid);
        sbits[tid + 256] = __ldcg(curbits + tid + 256);
        __syncthreads();

        // build per-row ascending firing lists: thread (row = tid>>4, g = tid&15)
        {
            const int brow = tid >> 4;
            const int g    = tid & 15;
            const unsigned* wp = sbits + brow * 32 + 4 * (g >> 1);
            ull M = 0;
#pragma unroll
            for (int r = 0; r < 4; ++r) {
                unsigned w = wp[r];
                unsigned h = (g & 1) ? (w >> 16) : (w & 0xFFFFu);
                M |= spread4(h) << r;
            }
            unsigned cnt = __popcll(M);
            unsigned inc = cnt;
#pragma unroll
            for (int d2 = 1; d2 < 16; d2 <<= 1) {
                unsigned tt = __shfl_up_sync(0xffffffffu, inc, d2, 16);
                if ((tid & 15) >= d2) inc += tt;
            }
            unsigned wpos = brow * 1024 + (inc - cnt);
            int jb = g * 64;
            while (M) {
                int pos = __ffsll(M) - 1;
                M &= M - 1;
                slist[wpos++] = (unsigned)((jb + pos) << 12);  // byte offset j*4096
            }
            if ((tid & 15) == 15) scount[brow] = inc;
        }
        __syncthreads();

        // consume: pure FADD2 stream over firing rows (ascending j)
        float4 G[2];
#pragma unroll
        for (int rr = 0; rr < 2; ++rr) {
            const int row = 2 * u + rr;
            const int n = scount[row];
            const unsigned* lp = slist + row * 1024;
            ull a0 = 0ull, a1 = 0ull;
            int i = 0;
            for (; i + 4 <= n; i += 4) {
                uint4 o = *(const uint4*)(lp + i);
                ulonglong2 v0 = *(const ulonglong2*)(Vb + o.x);
                a0 = padd(a0, v0.x); a1 = padd(a1, v0.y);
                ulonglong2 v1 = *(const ulonglong2*)(Vb + o.y);
                a0 = padd(a0, v1.x); a1 = padd(a1, v1.y);
                ulonglong2 v2 = *(const ulonglong2*)(Vb + o.z);
                a0 = padd(a0, v2.x); a1 = padd(a1, v2.y);
                ulonglong2 v3 = *(const ulonglong2*)(Vb + o.w);
                a0 = padd(a0, v3.x); a1 = padd(a1, v3.y);
            }
            for (; i < n; ++i) {
                ulonglong2 v = *(const ulonglong2*)(Vb + lp[i]);
                a0 = padd(a0, v.x); a1 = padd(a1, v.y);
            }
            float2 g01 = *(float2*)&a0;
            float2 g23 = *(float2*)&a1;
            G[rr] = make_float4(g01.x, g01.y, g23.x, g23.y);
        }

        // membrane (frozen semantics) + new spike bits
        unsigned nps[2];
#pragma unroll
        for (int rr = 0; rr < 2; ++rr) {
            float m[4], gg[4] = {G[rr].x, G[rr].y, G[rr].z, G[rr].w};
            float zv[4] = {zz[rr].x, zz[rr].y, zz[rr].z, zz[rr].w};
            float mv[4] = {mem2[rr].x, mem2[rr].y, mem2[rr].z, mem2[rr].w};
            float bb[4] = {bv4.x, bv4.y, bv4.z, bv4.w};
            unsigned np = 0;
#pragma unroll
            for (int k = 0; k < 4; ++k) {
                float rst = ((ps2[rr] >> k) & 1u) ? 1.0f : 0.0f;
                m[k] = __fsub_rn(__fadd_rn(__fadd_rn(
                           __fmaf_rn(0.95f, mv[k], zv[k]), gg[k]), bb[k]), rst);
                np |= (m[k] > 1.0f ? 1u : 0u) << k;
            }
            mem2[rr] = make_float4(m[0], m[1], m[2], m[3]);
            ps2[rr] = np;
            nps[rr] = np;
        }

        // publish: 4 ballots per row, one STG.128 per row from lane 0
        unsigned* dstb = &g_bits[(t + 1) % 3][0][0];
#pragma unroll
        for (int rr = 0; rr < 2; ++rr) {
            unsigned b0 = __ballot_sync(0xffffffffu, (nps[rr] >> 0) & 1u);
            unsigned b1 = __ballot_sync(0xffffffffu, (nps[rr] >> 1) & 1u);
            unsigned b2 = __ballot_sync(0xffffffffu, (nps[rr] >> 2) & 1u);
            unsigned b3 = __ballot_sync(0xffffffffu, (nps[rr] >> 3) & 1u);
            if (lane == 0) {
                int row = r0 + 2 * u + rr;
                *(uint4*)(dstb + row * 32 + 4 * cg) = make_uint4(b0, b1, b2, b3);
            }
        }

        grid_barrier();
    }

    // Heads: tail spikes in g_bits[2] (new layout: word = 4*(j>>7) + (j&3),
    // bit = (j>>2)&31). No feedback -> ulp-order harmless; flat chains.
    const unsigned* tail = &g_bits[2][0][0];
    if (tid < 22) {
        int r = bid * 2 + tid / 11;
        int o = tid % 11;
        const float* Wp; int stride; float bo_;
        if (o < 6)       { Wp = W_pol  + o;       stride = NA; bo_ = b_pol[o]; }
        else if (o < 10) { Wp = W_size + (o - 6); stride = NS; bo_ = b_size[o - 6]; }
        else             { Wp = W_val;            stride = 1;  bo_ = b_val[0]; }
        float s = 0.f;
        for (int j = 0; j < HID; ++j) {
            unsigned word = __ldcg(tail + r * 32 + (4 * (j >> 7) + (j & 3)));
            if ((word >> ((j >> 2) & 31)) & 1u)
                s = __fadd_rn(s, Wp[(size_t)j * stride]);
        }
        float val = __fadd_rn(s, bo_);
        if (o < 6)       out[r * NA + o] = val;
        else if (o < 10) out[BATCH * NA + r * NS + (o - 6)] = val;
        else             out[BATCH * NA + BATCH * NS + r] = val;
    }
}

// ---------------------------------------------------------------------------
extern "C" void kernel_launch(void* const* d_in, const int* in_sizes, int n_in,
                              void* d_out, int out_size) {
    const float* x      = (const float*)d_in[0];
    const float* W_enc  = (const float*)d_in[1];
    const float* b_enc  = (const float*)d_in[2];
    const float* V      = (const float*)d_in[3];
    const float* b_v    = (const float*)d_in[4];
    const float* W_pol  = (const float*)d_in[5];
    const float* b_pol  = (const float*)d_in[6];
    const float* W_size = (const float*)d_in[7];
    const float* b_size = (const float*)d_in[8];
    const float* W_val  = (const float*)d_in[9];
    const float* b_val  = (const float*)d_in[10];
    float* out = (float*)d_out;

    cudaFuncSetAttribute(scan_kernel,
        cudaFuncAttributeMaxDynamicSharedMemorySize, SMEM_SCAN);

    dim3 eg(HID / 128, (BATCH * SEQ) / 128);
    encode_kernel<<<eg, 256>>>(x, W_enc, b_enc);

    scan_kernel<<<GRID_SCAN, 256, SMEM_SCAN>>>(V, b_v, W_pol, b_pol,
                                               W_size, b_size, W_val, b_val, out);
}

// round 13
// speedup vs baseline: 2.3046x; 1.2841x over previous
#include <cuda_runtime.h>
#include <cstdint>

#define BATCH 256
#define SEQ   512
#define DIM   512
#define HID   1024
#define NA    6
#define NS    4

typedef unsigned long long ull;

// ---------------------------------------------------------------------------
// Device scratch (static; no cudaMalloc allowed)
// ---------------------------------------------------------------------------
__device__ float    g_z[(size_t)SEQ * BATCH * HID];       // z [S][B][H]
__device__ __align__(16) unsigned g_bits[3][BATCH][HID / 32]; // spike bitmasks
__device__ unsigned g_barCount;                            // zero-init at load
__device__ unsigned g_barGen;                              // monotonic

#define GRID_SCAN 128
// dynamic smem: sbits[512] + scount[16]+pad[16] + slist[16][1024]
#define SMEM_SCAN ((512 + 32 + 16 * 1024) * 4)

// ---------------------------------------------------------------------------
// Grid barrier (128 blocks, 1/SM -> co-resident; self-restoring across replays)
// ---------------------------------------------------------------------------
__device__ __forceinline__ void grid_barrier() {
    __threadfence();
    __syncthreads();
    if (threadIdx.x == 0) {
        unsigned gen = *(volatile unsigned*)&g_barGen;
        unsigned arr = atomicAdd(&g_barCount, 1u);
        if (arr == GRID_SCAN - 1) {
            g_barCount = 0;
            __threadfence();
            *(volatile unsigned*)&g_barGen = gen + 1u;
        } else {
            while (*(volatile unsigned*)&g_barGen == gen) { }
        }
    }
    __syncthreads();
}

// Packed f32x2 add: each half rounds exactly like scalar add.rn.f32
// (== the reference's fma(1.0, v, acc) chain step).
__device__ __forceinline__ ull padd(ull a, ull b) {
    ull r;
    asm("add.rn.f32x2 %0, %1, %2;" : "=l"(r) : "l"(a), "l"(b));
    return r;
}

// spread 16 bits: bit i -> bit 4i of a 64-bit word
__device__ __forceinline__ ull spread4(unsigned h) {
    ull x = h;
    x = (x | (x << 24)) & 0x000000FF000000FFull;
    x = (x | (x << 12)) & 0x000F000F000F000Full;
    x = (x | (x << 6))  & 0x0303030303030303ull;
    x = (x | (x << 3))  & 0x1111111111111111ull;
    return x;
}

// ---------------------------------------------------------------------------
// Encode: z = relu(x @ W_enc + b_enc). FLAT ascending-k single-accumulator
// FFMA chain per element; bias-add and relu separately rounded. (Frozen.)
// Register-prefetch double buffering. Block (0,0) also zeroes g_bits[0].
// ---------------------------------------------------------------------------
__global__ void __launch_bounds__(256, 2) encode_kernel(
    const float* __restrict__ X, const float* __restrict__ W,
    const float* __restrict__ bias)
{
    __shared__ float As[16][128];
    __shared__ float Bs[16][128];

    const int bm = blockIdx.y;
    const int bn = blockIdx.x;
    const int tid = threadIdx.x;

    if (bm == 0 && bn == 0) {
        unsigned* bz = &g_bits[0][0][0];
#pragma unroll
        for (int l = 0; l < (BATCH * (HID / 32)) / 256; ++l)
            bz[tid + l * 256] = 0u;
    }

    const int trow = (tid >> 4) * 8;
    const int tcol = (tid & 15) * 8;

    const float* A0 = X + (size_t)bm * 128 * DIM;
    const float* B0 = W + bn * 128;

    const int ar0 = tid >> 2,          ak0 = (tid & 3) * 4;
    const int ar1 = (tid + 256) >> 2,  ak1 = ((tid + 256) & 3) * 4;
    const int br0 = tid >> 5,          bc0 = (tid & 31) * 4;
    const int br1 = (tid + 256) >> 5,  bc1 = ((tid + 256) & 31) * 4;

    float acc[8][8];
#pragma unroll
    for (int i = 0; i < 8; ++i)
#pragma unroll
        for (int j = 0; j < 8; ++j) acc[i][j] = 0.f;

    float4 pa0 = *(const float4*)(A0 + (size_t)ar0 * DIM + ak0);
    float4 pa1 = *(const float4*)(A0 + (size_t)ar1 * DIM + ak1);
    float4 pb0 = *(const float4*)(B0 + (size_t)br0 * HID + bc0);
    float4 pb1 = *(const float4*)(B0 + (size_t)br1 * HID + bc1);

    for (int kt = 0; kt < DIM; kt += 16) {
        As[ak0 + 0][ar0] = pa0.x; As[ak0 + 1][ar0] = pa0.y;
        As[ak0 + 2][ar0] = pa0.z; As[ak0 + 3][ar0] = pa0.w;
        As[ak1 + 0][ar1] = pa1.x; As[ak1 + 1][ar1] = pa1.y;
        As[ak1 + 2][ar1] = pa1.z; As[ak1 + 3][ar1] = pa1.w;
        *(float4*)&Bs[br0][bc0] = pb0;
        *(float4*)&Bs[br1][bc1] = pb1;
        __syncthreads();

        if (kt + 16 < DIM) {
            pa0 = *(const float4*)(A0 + (size_t)ar0 * DIM + (kt + 16) + ak0);
            pa1 = *(const float4*)(A0 + (size_t)ar1 * DIM + (kt + 16) + ak1);
            pb0 = *(const float4*)(B0 + (size_t)(kt + 16 + br0) * HID + bc0);
            pb1 = *(const float4*)(B0 + (size_t)(kt + 16 + br1) * HID + bc1);
        }

#pragma unroll
        for (int kk = 0; kk < 16; ++kk) {
            float ra[8], rb[8];
#pragma unroll
            for (int i = 0; i < 8; ++i) ra[i] = As[kk][trow + i];
#pragma unroll
            for (int j = 0; j < 8; ++j) rb[j] = Bs[kk][tcol + j];
#pragma unroll
            for (int i = 0; i < 8; ++i)
#pragma unroll
                for (int j = 0; j < 8; ++j)
                    acc[i][j] = __fmaf_rn(ra[i], rb[j], acc[i][j]);
        }
        __syncthreads();
    }

    const int m0 = bm * 128 + trow;
    const int n0 = bn * 128 + tcol;
    float bb[8];
#pragma unroll
    for (int j = 0; j < 8; ++j) bb[j] = bias[n0 + j];
#pragma unroll
    for (int i = 0; i < 8; ++i) {
        int m = m0 + i;
        int b = m >> 9;
        int s = m & 511;
        float* dst = g_z + ((size_t)s * BATCH + b) * HID + n0;
        float r[8];
#pragma unroll
        for (int j = 0; j < 8; ++j)
            r[j] = fmaxf(__fadd_rn(acc[i][j], bb[j]), 0.f);
        ((float4*)dst)[0] = make_float4(r[0], r[1], r[2], r[3]);
        ((float4*)dst)[1] = make_float4(r[4], r[5], r[6], r[7]);
    }
}

// ---------------------------------------------------------------------------
// Scan: persistent, 128 blocks x 512 threads (16 warps). Block = 16 rows x
// 128 cols. Warp u owns row u; lane owns 4 adjacent cols (c = c0 + 4*lane).
//
// Bit layout: word (row, 4*cg + r), bit l  <->  col/j = 128*cg + 4*l + r.
// Per step: masks -> per-row ascending firing-index lists (byte offsets
// j*4096) in smem, then a pure FADD2 stream over LDG.128 V rows, unroll x8
// for MLP. Exactness: visits = exactly the firing j's ascending == the
// reference's flat ascending-k chain. Membrane: fma(0.95, mem, z) then
// +G, +bv, -rst separately rounded. (Frozen semantics.)
// ---------------------------------------------------------------------------
__global__ void __launch_bounds__(512, 1) scan_kernel(
    const float* __restrict__ V,      const float* __restrict__ b_v,
    const float* __restrict__ W_pol,  const float* __restrict__ b_pol,
    const float* __restrict__ W_size, const float* __restrict__ b_size,
    const float* __restrict__ W_val,  const float* __restrict__ b_val,
    float* __restrict__ out)
{
    extern __shared__ unsigned smx[];
    unsigned* sbits  = smx;            // [16][32]
    unsigned* scount = smx + 512;      // [16] (+16 pad)
    unsigned* slist  = smx + 544;      // [16][1024]

    const int tid  = threadIdx.x;
    const int bid  = blockIdx.x;
    const int rg   = bid >> 3;
    const int cg   = bid & 7;
    const int r0   = rg * 16;
    const int c0   = cg * 128;
    const int u    = tid >> 5;          // warp id 0..15 -> row u
    const int lane = tid & 31;
    const int c    = c0 + 4 * lane;     // first of 4 adjacent cols

    const char* Vb = (const char*)V + (size_t)c * 4;

    float4 mem4 = make_float4(0.f, 0.f, 0.f, 0.f);
    unsigned ps = 0u;                   // 4 spike bits (cols c..c+3)

    const float4 bv4 = *(const float4*)(b_v + c);

    for (int t = 0; t < SEQ; ++t) {
        // z prefetch (independent -> latency hidden under list build)
        float4 zz = *(const float4*)(g_z +
                      ((size_t)t * BATCH + r0 + u) * HID + c);

        // stage this block's 16 rows of spike bits (512 words, 1 per thread)
        const unsigned* curbits = &g_bits[t % 3][0][0] + (size_t)r0 * 32;
        sbits[tid] = __ldcg(curbits + tid);
        __syncthreads();

        // build per-row ascending firing lists (threads 0..255)
        if (tid < 256) {
            const int brow = tid >> 4;
            const int g    = tid & 15;
            const unsigned* wp = sbits + brow * 32 + 4 * (g >> 1);
            ull M = 0;
#pragma unroll
            for (int r = 0; r < 4; ++r) {
                unsigned w = wp[r];
                unsigned h = (g & 1) ? (w >> 16) : (w & 0xFFFFu);
                M |= spread4(h) << r;
            }
            unsigned cnt = __popcll(M);
            unsigned inc = cnt;
#pragma unroll
            for (int d2 = 1; d2 < 16; d2 <<= 1) {
                unsigned tt = __shfl_up_sync(0xffffffffu, inc, d2, 16);
                if ((tid & 15) >= d2) inc += tt;
            }
            unsigned wpos = brow * 1024 + (inc - cnt);
            int jb = g * 64;
            while (M) {
                int pos = __ffsll(M) - 1;
                M &= M - 1;
                slist[wpos++] = (unsigned)((jb + pos) << 12);  // byte offs j*4096
            }
            if ((tid & 15) == 15) scount[brow] = inc;
        }
        __syncthreads();

        // consume: pure FADD2 stream over this row's firing list, unroll x8
        const int n = scount[u];
        const unsigned* lp = slist + u * 1024;
        ull a0 = 0ull, a1 = 0ull;
        int i = 0;
        for (; i + 8 <= n; i += 8) {
            uint4 oa = *(const uint4*)(lp + i);
            uint4 ob = *(const uint4*)(lp + i + 4);
            ulonglong2 v0 = *(const ulonglong2*)(Vb + oa.x);
            ulonglong2 v1 = *(const ulonglong2*)(Vb + oa.y);
            ulonglong2 v2 = *(const ulonglong2*)(Vb + oa.z);
            ulonglong2 v3 = *(const ulonglong2*)(Vb + oa.w);
            ulonglong2 v4 = *(const ulonglong2*)(Vb + ob.x);
            ulonglong2 v5 = *(const ulonglong2*)(Vb + ob.y);
            ulonglong2 v6 = *(const ulonglong2*)(Vb + ob.z);
            ulonglong2 v7 = *(const ulonglong2*)(Vb + ob.w);
            a0 = padd(a0, v0.x); a1 = padd(a1, v0.y);
            a0 = padd(a0, v1.x); a1 = padd(a1, v1.y);
            a0 = padd(a0, v2.x); a1 = padd(a1, v2.y);
            a0 = padd(a0, v3.x); a1 = padd(a1, v3.y);
            a0 = padd(a0, v4.x); a1 = padd(a1, v4.y);
            a0 = padd(a0, v5.x); a1 = padd(a1, v5.y);
            a0 = padd(a0, v6.x); a1 = padd(a1, v6.y);
            a0 = padd(a0, v7.x); a1 = padd(a1, v7.y);
        }
        for (; i < n; ++i) {
            ulonglong2 v = *(const ulonglong2*)(Vb + lp[i]);
            a0 = padd(a0, v.x); a1 = padd(a1, v.y);
        }
        float2 g01 = *(float2*)&a0;
        float2 g23 = *(float2*)&a1;

        // membrane (frozen semantics)
        float gg[4] = {g01.x, g01.y, g23.x, g23.y};
        float zv[4] = {zz.x, zz.y, zz.z, zz.w};
        float mv[4] = {mem4.x, mem4.y, mem4.z, mem4.w};
        float bb[4] = {bv4.x, bv4.y, bv4.z, bv4.w};
        float m[4];
        unsigned np = 0;
#pragma unroll
        for (int k = 0; k < 4; ++k) {
            float rst = ((ps >> k) & 1u) ? 1.0f : 0.0f;
            m[k] = __fsub_rn(__fadd_rn(__fadd_rn(
                       __fmaf_rn(0.95f, mv[k], zv[k]), gg[k]), bb[k]), rst);
            np |= (m[k] > 1.0f ? 1u : 0u) << k;
        }
        mem4 = make_float4(m[0], m[1], m[2], m[3]);
        ps = np;

        // publish: 4 ballots, one STG.128 from lane 0
        unsigned b0 = __ballot_sync(0xffffffffu, (np >> 0) & 1u);
        unsigned b1 = __ballot_sync(0xffffffffu, (np >> 1) & 1u);
        unsigned b2 = __ballot_sync(0xffffffffu, (np >> 2) & 1u);
        unsigned b3 = __ballot_sync(0xffffffffu, (np >> 3) & 1u);
        if (lane == 0) {
            unsigned* dstb = &g_bits[(t + 1) % 3][0][0];
            *(uint4*)(dstb + (r0 + u) * 32 + 4 * cg) = make_uint4(b0, b1, b2, b3);
        }

        grid_barrier();
    }

    // Heads: tail spikes in g_bits[2] (layout: word = 4*(j>>7) + (j&3),
    // bit = (j>>2)&31). No feedback -> ulp-order harmless; flat chains.
    const unsigned* tail = &g_bits[2][0][0];
    if (tid < 22) {
        int r = bid * 2 + tid / 11;
        int o = tid % 11;
        const float* Wp; int stride; float bo_;
        if (o < 6)       { Wp = W_pol  + o;       stride = NA; bo_ = b_pol[o]; }
        else if (o < 10) { Wp = W_size + (o - 6); stride = NS; bo_ = b_size[o - 6]; }
        else             { Wp = W_val;            stride = 1;  bo_ = b_val[0]; }
        float s = 0.f;
        for (int j = 0; j < HID; ++j) {
            unsigned word = __ldcg(tail + r * 32 + (4 * (j >> 7) + (j & 3)));
            if ((word >> ((j >> 2) & 31)) & 1u)
                s = __fadd_rn(s, Wp[(size_t)j * stride]);
        }
        float val = __fadd_rn(s, bo_);
        if (o < 6)       out[r * NA + o] = val;
        else if (o < 10) out[BATCH * NA + r * NS + (o - 6)] = val;
        else             out[BATCH * NA + BATCH * NS + r] = val;
    }
}

// ---------------------------------------------------------------------------
extern "C" void kernel_launch(void* const* d_in, const int* in_sizes, int n_in,
                              void* d_out, int out_size) {
    const float* x      = (const float*)d_in[0];
    const float* W_enc  = (const float*)d_in[1];
    const float* b_enc  = (const float*)d_in[2];
    const float* V      = (const float*)d_in[3];
    const float* b_v    = (const float*)d_in[4];
    const float* W_pol  = (const float*)d_in[5];
    const float* b_pol  = (const float*)d_in[6];
    const float* W_size = (const float*)d_in[7];
    const float* b_size = (const float*)d_in[8];
    const float* W_val  = (const float*)d_in[9];
    const float* b_val  = (const float*)d_in[10];
    float* out = (float*)d_out;

    cudaFuncSetAttribute(scan_kernel,
        cudaFuncAttributeMaxDynamicSharedMemorySize, SMEM_SCAN);

    dim3 eg(HID / 128, (BATCH * SEQ) / 128);
    encode_kernel<<<eg, 256>>>(x, W_enc, b_enc);

    scan_kernel<<<GRID_SCAN, 512, SMEM_SCAN>>>(V, b_v, W_pol, b_pol,
                                               W_size, b_size, W_val, b_val, out);
}